// round 6
// baseline (speedup 1.0000x reference)
#include <cuda_runtime.h>
#include <cuda_fp16.h>
#include <math.h>
#include <stdint.h>

#define NVOX 40000
#define NQ   8192
#define KK   96
#define C    128
#define FF   256
#define NH   8
#define DH   16
#define KVROW 136

// weight split buffer offsets (floats)
#define W_INW  0
#define W_OUTW 49152
#define W_L1W  65536
#define W_L2W  98304
#define W_FINW 131072
#define W_TOT  147456

// ---------------- scratch (device globals; no allocation) ----------------
__device__ float  g_kf_hi[NVOX * C],  g_kf_lo[NVOX * C];
__device__ __half g_KVh[NVOX * 2 * C];
__device__ float  g_qf_hi[NQ * C],    g_qf_lo[NQ * C];
__device__ float  g_q[NQ * C];
__device__ float  g_ctx_hi[NQ * C],   g_ctx_lo[NQ * C];
__device__ float  g_att[NQ * C];
__device__ float  g_hn_hi[NQ * C],    g_hn_lo[NQ * C];
__device__ float  g_a1_hi[NQ * FF],   g_a1_lo[NQ * FF];
__device__ float  g_x_hi[NQ * C],     g_x_lo[NQ * C];
__device__ float  g_w_hi[W_TOT],      g_w_lo[W_TOT];

// ---------------- helpers ----------------
__device__ __forceinline__ float tf32r(float x) {
    uint32_t u;
    asm("cvt.rna.tf32.f32 %0, %1;" : "=r"(u) : "f"(x));
    return __uint_as_float(u);
}

// fragment-major column permutation within each 32-col block:
// position = (c&3)*8 + ((c&31)>>2), preserving the 32-block.
__device__ __forceinline__ int pcol(int c) {
    return (c & ~31) + ((c & 3) << 3) + ((c & 31) >> 2);
}

__device__ __forceinline__ void mma8(float* d, const float* a, const float* b) {
    asm volatile(
        "mma.sync.aligned.m16n8k8.row.col.f32.tf32.tf32.f32 "
        "{%0,%1,%2,%3}, {%4,%5,%6,%7}, {%8,%9}, {%0,%1,%2,%3};"
        : "+f"(d[0]), "+f"(d[1]), "+f"(d[2]), "+f"(d[3])
        : "r"(__float_as_uint(a[0])), "r"(__float_as_uint(a[1])),
          "r"(__float_as_uint(a[2])), "r"(__float_as_uint(a[3])),
          "r"(__float_as_uint(b[0])), "r"(__float_as_uint(b[1])));
}

// ---------------- weight hi/lo split (permuted layout) ----------------
__global__ void wsplit_kernel(const float* __restrict__ s0,
                              const float* __restrict__ s1,
                              const float* __restrict__ s2,
                              const float* __restrict__ s3,
                              const float* __restrict__ s4)
{
    int i = blockIdx.x * 256 + threadIdx.x;
    if (i >= W_TOT) return;
    const float* s; int off, kd;
    if      (i < W_OUTW) { s = s0; off = W_INW;  kd = 128; }
    else if (i < W_L1W)  { s = s1; off = W_OUTW; kd = 128; }
    else if (i < W_L2W)  { s = s2; off = W_L1W;  kd = 128; }
    else if (i < W_FINW) { s = s3; off = W_L2W;  kd = 256; }
    else                 { s = s4; off = W_FINW; kd = 128; }
    int local = i - off;
    int row = local / kd, col = local % kd;
    float x = s[local];
    float h = tf32r(x);
    int dst = off + row * kd + pcol(col);
    g_w_hi[dst] = h;
    g_w_lo[dst] = tf32r(x - h);
}

// ---------------- per-voxel LN + positional feature -> permuted hi/lo ------
__global__ void kf_kernel(const float* __restrict__ vf,
                          const float* __restrict__ vc,
                          const float* __restrict__ g1,
                          const float* __restrict__ b1,
                          const float* __restrict__ kpw,
                          const float* __restrict__ kpb)
{
    int v    = blockIdx.x * 8 + (threadIdx.x >> 5);
    int lane = threadIdx.x & 31;
    if (v >= NVOX) return;

    float4 x = ((const float4*)(vf + (size_t)v * C))[lane];
    float s = x.x + x.y + x.z + x.w;
    float q = x.x * x.x + x.y * x.y + x.z * x.z + x.w * x.w;
#pragma unroll
    for (int o = 16; o; o >>= 1) {
        s += __shfl_xor_sync(0xffffffffu, s, o);
        q += __shfl_xor_sync(0xffffffffu, q, o);
    }
    float m   = s * (1.0f / 128.0f);
    float var = q * (1.0f / 128.0f) - m * m;
    float r   = rsqrtf(var + 1e-5f);

    float cx = vc[v * 3 + 0], cy = vc[v * 3 + 1], cz = vc[v * 3 + 2];

    const float* xv = &x.x;
#pragma unroll
    for (int j = 0; j < 4; j++) {
        int c = lane * 4 + j;
        float y  = (xv[j] - m) * r * g1[c] + b1[c];
        float kp = fmaxf(kpw[c * 3 + 0] * cx + kpw[c * 3 + 1] * cy +
                         kpw[c * 3 + 2] * cz + kpb[c], 0.0f);
        float t = y + kp;
        float hi = tf32r(t);
        int d = v * C + pcol(c);
        g_kf_hi[d] = hi;
        g_kf_lo[d] = tf32r(t - hi);
    }
}

// ---------------- row LayerNorm (norm2) -> permuted hi/lo ----------------
__global__ void ln_kernel(const float* __restrict__ in,
                          const float* __restrict__ g,
                          const float* __restrict__ b)
{
    int r    = blockIdx.x * 8 + (threadIdx.x >> 5);
    int lane = threadIdx.x & 31;

    float4 x = ((const float4*)(in + (size_t)r * C))[lane];
    float s = x.x + x.y + x.z + x.w;
    float q = x.x * x.x + x.y * x.y + x.z * x.z + x.w * x.w;
#pragma unroll
    for (int o = 16; o; o >>= 1) {
        s += __shfl_xor_sync(0xffffffffu, s, o);
        q += __shfl_xor_sync(0xffffffffu, q, o);
    }
    float m   = s * (1.0f / 128.0f);
    float var = q * (1.0f / 128.0f) - m * m;
    float rs  = rsqrtf(var + 1e-5f);

    const float* xv = &x.x;
#pragma unroll
    for (int j = 0; j < 4; j++) {
        int c = lane * 4 + j;
        float t = (xv[j] - m) * rs * g[c] + b[c];
        float hi = tf32r(t);
        int d = r * C + pcol(c);
        g_hn_hi[d] = hi;
        g_hn_lo[d] = tf32r(t - hi);
    }
}

// ---------------- query positional feature -> permuted hi/lo ----------------
__global__ void qfeat_kernel(const float* __restrict__ qc,
                             const float* __restrict__ qpw,
                             const float* __restrict__ qpb)
{
    int t = blockIdx.x * 256 + threadIdx.x;
    int n = t >> 7, c = t & 127;
    float x = qc[n * 3 + 0], y = qc[n * 3 + 1], z = qc[n * 3 + 2];
    float v = fmaxf(qpw[c * 3 + 0] * x + qpw[c * 3 + 1] * y +
                    qpw[c * 3 + 2] * z + qpb[c], 0.0f);
    float h = tf32r(v);
    int d = n * C + pcol(c);
    g_qf_hi[d] = h;
    g_qf_lo[d] = tf32r(v - h);
}

// ---------------- tensor-core GEMM (3xTF32, fragment-major + XOR swizzle) ---
// out[M,N] = A[M,Kd] @ W[N,Kd]^T (+bias)(+res)(relu)
// A,W in permuted hi/lo layout. CTA 64x64, 4 warps of 32x32.
// flags: 1=relu, 2=res, 4=half out, 8=f32 out, 16=permuted hi/lo out
__global__ __launch_bounds__(128)
void mma_gemm(const float* __restrict__ Ahi, const float* __restrict__ Alo,
              const float* __restrict__ Whi, const float* __restrict__ Wlo,
              const float* __restrict__ bias, const float* __restrict__ res,
              float* __restrict__ out32, __half* __restrict__ outh,
              float* __restrict__ ohi, float* __restrict__ olo,
              int N, int Kd, int flags)
{
    __shared__ float As[2][64][32];   // [hi/lo][row][swizzled permuted cols]
    __shared__ float Bs[2][64][32];

    const int tid  = threadIdx.x;
    const int m0   = blockIdx.x * 64;
    const int n0   = blockIdx.y * 64;
    const int lane = tid & 31;
    const int g    = lane >> 2;      // 0..7
    const int tig  = lane & 3;       // 0..3
    const int wm   = tid >> 6;       // 0..1
    const int wn   = (tid >> 5) & 1; // 0..1

    const int lr  = tid >> 3;        // loader row base 0..15
    const int q   = tid & 7;         // loader chunk 0..7
    const int sca = ((q ^ (lr & 7)) << 2);  // swizzled store col

    float acc[2][4][4];
#pragma unroll
    for (int t = 0; t < 2; t++)
#pragma unroll
        for (int j = 0; j < 4; j++)
#pragma unroll
            for (int e = 0; e < 4; e++) acc[t][j][e] = 0.0f;

    float4 ra0[4], ra1[4], rb0[4], rb1[4];
#pragma unroll
    for (int i = 0; i < 4; i++) {
        size_t ao = (size_t)(m0 + lr + i * 16) * Kd + q * 4;
        size_t bo = (size_t)(n0 + lr + i * 16) * Kd + q * 4;
        ra0[i] = *(const float4*)(Ahi + ao);
        ra1[i] = *(const float4*)(Alo + ao);
        rb0[i] = *(const float4*)(Whi + bo);
        rb1[i] = *(const float4*)(Wlo + bo);
    }

    for (int kc = 0; kc < Kd; kc += 32) {
#pragma unroll
        for (int i = 0; i < 4; i++) {
            int r = lr + i * 16;
            *(float4*)&As[0][r][sca] = ra0[i];
            *(float4*)&As[1][r][sca] = ra1[i];
            *(float4*)&Bs[0][r][sca] = rb0[i];
            *(float4*)&Bs[1][r][sca] = rb1[i];
        }
        __syncthreads();

        const bool more = (kc + 32) < Kd;
        if (more) {
#pragma unroll
            for (int i = 0; i < 4; i++) {
                size_t ao = (size_t)(m0 + lr + i * 16) * Kd + kc + 32 + q * 4;
                size_t bo = (size_t)(n0 + lr + i * 16) * Kd + kc + 32 + q * 4;
                ra0[i] = *(const float4*)(Ahi + ao);
                ra1[i] = *(const float4*)(Alo + ao);
                rb0[i] = *(const float4*)(Whi + bo);
                rb1[i] = *(const float4*)(Wlo + bo);
            }
        }

#pragma unroll
        for (int s = 0; s < 2; s++) {
            const int cs = (((2 * tig + s) ^ g) << 2);
            float4 Ah[4], Al[4], Bh[4], Bl[4];
#pragma unroll
            for (int r = 0; r < 4; r++) {
                int ar = wm * 32 + g + 8 * r;
                int br = wn * 32 + g + 8 * r;
                Ah[r] = *(const float4*)&As[0][ar][cs];
                Al[r] = *(const float4*)&As[1][ar][cs];
                Bh[r] = *(const float4*)&Bs[0][br][cs];
                Bl[r] = *(const float4*)&Bs[1][br][cs];
            }
#pragma unroll
            for (int k2 = 0; k2 < 2; k2++) {
                float ah[2][4], al[2][4], bh[4][2], bl[4][2];
#pragma unroll
                for (int t = 0; t < 2; t++) {
                    float4 v0 = Ah[2 * t], v1 = Ah[2 * t + 1];
                    float4 w0 = Al[2 * t], w1 = Al[2 * t + 1];
                    ah[t][0] = k2 ? v0.z : v0.x;
                    ah[t][1] = k2 ? v1.z : v1.x;
                    ah[t][2] = k2 ? v0.w : v0.y;
                    ah[t][3] = k2 ? v1.w : v1.y;
                    al[t][0] = k2 ? w0.z : w0.x;
                    al[t][1] = k2 ? w1.z : w1.x;
                    al[t][2] = k2 ? w0.w : w0.y;
                    al[t][3] = k2 ? w1.w : w1.y;
                }
#pragma unroll
                for (int j = 0; j < 4; j++) {
                    bh[j][0] = k2 ? Bh[j].z : Bh[j].x;
                    bh[j][1] = k2 ? Bh[j].w : Bh[j].y;
                    bl[j][0] = k2 ? Bl[j].z : Bl[j].x;
                    bl[j][1] = k2 ? Bl[j].w : Bl[j].y;
                }
#pragma unroll
                for (int t = 0; t < 2; t++)
#pragma unroll
                    for (int j = 0; j < 4; j++) {
                        mma8(acc[t][j], ah[t], bh[j]);
                        mma8(acc[t][j], ah[t], bl[j]);
                        mma8(acc[t][j], al[t], bh[j]);
                    }
            }
        }
        __syncthreads();
    }

    // epilogue
#pragma unroll
    for (int t = 0; t < 2; t++) {
#pragma unroll
        for (int j = 0; j < 4; j++) {
            int row0 = m0 + wm * 32 + t * 16 + g;
            int col  = n0 + wn * 32 + j * 8 + 2 * tig;
            float2 bi = make_float2(bias[col], bias[col + 1]);
#pragma unroll
            for (int h2 = 0; h2 < 2; h2++) {
                int row = row0 + h2 * 8;
                float x0 = acc[t][j][h2 * 2 + 0] + bi.x;
                float x1 = acc[t][j][h2 * 2 + 1] + bi.y;
                size_t o = (size_t)row * N + col;
                if (flags & 2) {
                    float2 r2 = *(const float2*)(res + o);
                    x0 += r2.x; x1 += r2.y;
                }
                if (flags & 1) { x0 = fmaxf(x0, 0.0f); x1 = fmaxf(x1, 0.0f); }
                if (flags & 8)  *(float2*)(out32 + o) = make_float2(x0, x1);
                if (flags & 4)  *(__half2*)(outh + o) = __floats2half2_rn(x0, x1);
                if (flags & 16) {
                    float h0 = tf32r(x0), h1 = tf32r(x1);
                    size_t p0 = (size_t)row * N + pcol(col);
                    size_t p1 = (size_t)row * N + pcol(col + 1);
                    ohi[p0] = h0;            ohi[p1] = h1;
                    olo[p0] = tf32r(x0 - h0); olo[p1] = tf32r(x1 - h1);
                }
            }
        }
    }
}

// ---------------- attention: one block per query, 128 threads ----------------
// Scores read K head-slices directly from L2 into regs; V staged in smem.
__global__ __launch_bounds__(128)
void attn_kernel(const int* __restrict__ kidx)
{
    __shared__ int   idx_s[KK];
    __shared__ float p_s[NH][KK];
    __shared__ __align__(16) __half kv_s[KK * KVROW];

    const int n = blockIdx.x;
    const int t = threadIdx.x;
    const int h = t >> 4, l16 = t & 15;

    if (t < KK) idx_s[t] = kidx[n * KK + t];
    __syncthreads();

    // prefetch this thread's 6 K head-slices (32B each) from L2
    uint4 kreg[6][2];
    int vidx[6];
#pragma unroll
    for (int m = 0; m < 6; m++) {
        int v = idx_s[l16 + m * 16];
        vidx[m] = v;
        if (v >= 0) {
            const uint4* p = (const uint4*)(g_KVh + (size_t)v * 256 + h * 16);
            kreg[m][0] = p[0];
            kreg[m][1] = p[1];
        }
    }

    float qreg[16];
    {
        const float* qp = g_q + (size_t)n * C + h * 16;
#pragma unroll
        for (int d = 0; d < 16; d++) qreg[d] = qp[d];
    }

    float sc[6];
#pragma unroll
    for (int m = 0; m < 6; m++) {
        const __half2* kp = (const __half2*)&kreg[m][0];
        float s = 0.0f;
#pragma unroll
        for (int d = 0; d < 8; d++) {
            float2 kv2 = __half22float2(kp[d]);
            s += qreg[2 * d] * kv2.x + qreg[2 * d + 1] * kv2.y;
        }
        sc[m] = s * 0.25f;
    }

    float mx = -1e30f;
#pragma unroll
    for (int m = 0; m < 6; m++)
        if (vidx[m] >= 0) mx = fmaxf(mx, sc[m]);
#pragma unroll
    for (int o = 8; o; o >>= 1)
        mx = fmaxf(mx, __shfl_xor_sync(0xffffffffu, mx, o, 16));

    float p[6];
    float sum = 0.0f;
#pragma unroll
    for (int m = 0; m < 6; m++) {
        p[m] = (vidx[m] >= 0) ? __expf(sc[m] - mx) : 0.0f;
        sum += p[m];
    }
#pragma unroll
    for (int o = 8; o; o >>= 1)
        sum += __shfl_xor_sync(0xffffffffu, sum, o, 16);
    const float inv = 1.0f / sum;
#pragma unroll
    for (int m = 0; m < 6; m++) p_s[h][l16 + m * 16] = p[m] * inv;

    // stage V rows (second 256B half of each KV row)
    const int rg = t >> 4;
    const int pp = t & 15;
#pragma unroll
    for (int i = 0; i < 12; i++) {
        int k = i * 8 + rg;
        int v = idx_s[k];
        uint4 d = make_uint4(0, 0, 0, 0);
        if (v >= 0) d = ((const uint4*)(g_KVh + (size_t)v * 256))[16 + pp];
        *(uint4*)(&kv_s[k * KVROW + pp * 8]) = d;
    }
    __syncthreads();

    float acc = 0.0f;
#pragma unroll 8
    for (int k = 0; k < KK; k++)
        acc += p_s[h][k] * __half2float(kv_s[k * KVROW + t]);

    float hi = tf32r(acc);
    int d = n * C + pcol(t);
    g_ctx_hi[d] = hi;
    g_ctx_lo[d] = tf32r(acc - hi);
}

// ---------------- host launch ----------------
extern "C" void kernel_launch(void* const* d_in, const int* in_sizes, int n_in,
                              void* d_out, int out_size)
{
    const float* vf   = (const float*)d_in[0];
    const float* vc   = (const float*)d_in[1];
    const float* qc   = (const float*)d_in[2];
    const int*   kidx = (const int*)  d_in[3];
    const float* n1g  = (const float*)d_in[4];
    const float* n1b  = (const float*)d_in[5];
    const float* qpw  = (const float*)d_in[6];
    const float* qpb  = (const float*)d_in[7];
    const float* kpw  = (const float*)d_in[8];
    const float* kpb  = (const float*)d_in[9];
    const float* inw  = (const float*)d_in[10];
    const float* inb  = (const float*)d_in[11];
    const float* outw = (const float*)d_in[12];
    const float* outb = (const float*)d_in[13];
    const float* n2g  = (const float*)d_in[14];
    const float* n2b  = (const float*)d_in[15];
    const float* l1w  = (const float*)d_in[16];
    const float* l1b  = (const float*)d_in[17];
    const float* l2w  = (const float*)d_in[18];
    const float* l2b  = (const float*)d_in[19];
    const float* fw   = (const float*)d_in[20];
    const float* fb   = (const float*)d_in[21];
    float* out = (float*)d_out;

    float *p_kf_hi, *p_kf_lo, *p_qf_hi, *p_qf_lo, *p_q, *p_ctx_hi, *p_ctx_lo;
    float *p_att, *p_hn_hi, *p_hn_lo, *p_a1_hi, *p_a1_lo, *p_x_hi, *p_x_lo;
    float *p_w_hi, *p_w_lo;
    __half* p_KVh;
    cudaGetSymbolAddress((void**)&p_kf_hi,  g_kf_hi);
    cudaGetSymbolAddress((void**)&p_kf_lo,  g_kf_lo);
    cudaGetSymbolAddress((void**)&p_KVh,    g_KVh);
    cudaGetSymbolAddress((void**)&p_qf_hi,  g_qf_hi);
    cudaGetSymbolAddress((void**)&p_qf_lo,  g_qf_lo);
    cudaGetSymbolAddress((void**)&p_q,      g_q);
    cudaGetSymbolAddress((void**)&p_ctx_hi, g_ctx_hi);
    cudaGetSymbolAddress((void**)&p_ctx_lo, g_ctx_lo);
    cudaGetSymbolAddress((void**)&p_att,    g_att);
    cudaGetSymbolAddress((void**)&p_hn_hi,  g_hn_hi);
    cudaGetSymbolAddress((void**)&p_hn_lo,  g_hn_lo);
    cudaGetSymbolAddress((void**)&p_a1_hi,  g_a1_hi);
    cudaGetSymbolAddress((void**)&p_a1_lo,  g_a1_lo);
    cudaGetSymbolAddress((void**)&p_x_hi,   g_x_hi);
    cudaGetSymbolAddress((void**)&p_x_lo,   g_x_lo);
    cudaGetSymbolAddress((void**)&p_w_hi,   g_w_hi);
    cudaGetSymbolAddress((void**)&p_w_lo,   g_w_lo);

    // 0) weights -> permuted tf32 hi/lo
    wsplit_kernel<<<(W_TOT + 255) / 256, 256>>>(inw, outw, l1w, l2w, fw);

    // 1) per-voxel LN + key positional feature (permuted hi/lo)
    kf_kernel<<<NVOX / 8, 256>>>(vf, vc, n1g, n1b, kpw, kpb);

    // 2) query positional feature (permuted hi/lo)
    qfeat_kernel<<<(NQ * C) / 256, 256>>>(qc, qpw, qpb);

    // 3) per-voxel K|V projection -> fp16 [NVOX,256]   (profiled launch)
    mma_gemm<<<dim3(NVOX / 64, 4), 128>>>(
        p_kf_hi, p_kf_lo, p_w_hi + W_INW + 128 * 128, p_w_lo + W_INW + 128 * 128,
        inb + 128, nullptr, nullptr, p_KVh, nullptr, nullptr, 256, 128, 4);

    // 4) q projection -> fp32 (plain)
    mma_gemm<<<dim3(NQ / 64, 2), 128>>>(
        p_qf_hi, p_qf_lo, p_w_hi + W_INW, p_w_lo + W_INW,
        inb, nullptr, p_q, nullptr, nullptr, nullptr, 128, 128, 8);

    // 5) sparse attention -> ctx (permuted hi/lo)
    attn_kernel<<<NQ, 128>>>(kidx);

    // 6) output projection -> attend fp32 (plain)
    mma_gemm<<<dim3(NQ / 64, 2), 128>>>(
        p_ctx_hi, p_ctx_lo, p_w_hi + W_OUTW, p_w_lo + W_OUTW,
        outb, nullptr, p_att, nullptr, nullptr, nullptr, 128, 128, 8);

    // 7) norm2 -> hn (permuted hi/lo)
    ln_kernel<<<NQ / 8, 256>>>(p_att, n2g, n2b);

    // 8) FFN up (relu) -> a1 (permuted hi/lo)
    mma_gemm<<<dim3(NQ / 64, 4), 128>>>(
        p_hn_hi, p_hn_lo, p_w_hi + W_L1W, p_w_lo + W_L1W,
        l1b, nullptr, nullptr, nullptr, p_a1_hi, p_a1_lo, 256, 128, 16 | 1);

    // 9) FFN down + residual(attend) -> x (permuted hi/lo)
    mma_gemm<<<dim3(NQ / 64, 2), 128>>>(
        p_a1_hi, p_a1_lo, p_w_hi + W_L2W, p_w_lo + W_L2W,
        l2b, p_att, nullptr, nullptr, p_x_hi, p_x_lo, 128, 256, 16 | 2);

    // 10) final projection + relu -> output fp32
    mma_gemm<<<dim3(NQ / 64, 2), 128>>>(
        p_x_hi, p_x_lo, p_w_hi + W_FINW, p_w_lo + W_FINW,
        fb, nullptr, out, nullptr, nullptr, nullptr, 128, 128, 8 | 1);
}

// round 7
// speedup vs baseline: 1.9719x; 1.9719x over previous
#include <cuda_runtime.h>
#include <cuda_fp16.h>
#include <math.h>
#include <stdint.h>

#define NVOX 40000
#define NQ   8192
#define KK   96
#define C    128
#define FF   256
#define NH   8
#define KVROW 136

// weight split buffer offsets (halfs)
#define W_INW  0
#define W_OUTW 49152
#define W_L1W  65536
#define W_L2W  98304
#define W_FINW 131072
#define W_TOT  147456

// ---------------- scratch (device globals; no allocation) ----------------
__device__ __half g_w_hi[W_TOT],     g_w_lo[W_TOT];
__device__ __half g_kf_hi[NVOX * C], g_kf_lo[NVOX * C];
__device__ __half g_KVh[NVOX * 2 * C];
__device__ __half g_qf_hi[NQ * C],   g_qf_lo[NQ * C];
__device__ float  g_q[NQ * C];
__device__ __half g_ctx_hi[NQ * C],  g_ctx_lo[NQ * C];
__device__ float  g_att[NQ * C];
__device__ __half g_hn_hi[NQ * C],   g_hn_lo[NQ * C];
__device__ __half g_a1_hi[NQ * FF],  g_a1_lo[NQ * FF];
__device__ __half g_x_hi[NQ * C],    g_x_lo[NQ * C];

// ---------------- helpers ----------------
__device__ __forceinline__ void h2split(float x, __half& h, __half& l) {
    h = __float2half(x);
    l = __float2half(x - __half2float(h));
}

__device__ __forceinline__ int skey(int r) { return (r ^ (r >> 2)) & 3; }

__device__ __forceinline__ void ldsm4(uint32_t* r, uint32_t addr) {
    asm volatile("ldmatrix.sync.aligned.m8n8.x4.shared.b16 {%0,%1,%2,%3}, [%4];"
                 : "=r"(r[0]), "=r"(r[1]), "=r"(r[2]), "=r"(r[3]) : "r"(addr));
}

__device__ __forceinline__ void mma16(float* d, const uint32_t* a, const uint32_t* b) {
    asm volatile(
        "mma.sync.aligned.m16n8k16.row.col.f32.f16.f16.f32 "
        "{%0,%1,%2,%3}, {%4,%5,%6,%7}, {%8,%9}, {%0,%1,%2,%3};"
        : "+f"(d[0]), "+f"(d[1]), "+f"(d[2]), "+f"(d[3])
        : "r"(a[0]), "r"(a[1]), "r"(a[2]), "r"(a[3]), "r"(b[0]), "r"(b[1]));
}

// ---------------- weight hi/lo split ----------------
__global__ void wsplit_kernel(const float* __restrict__ s0,
                              const float* __restrict__ s1,
                              const float* __restrict__ s2,
                              const float* __restrict__ s3,
                              const float* __restrict__ s4)
{
    int i = blockIdx.x * 256 + threadIdx.x;
    if (i >= W_TOT) return;
    const float* s; int off;
    if      (i < W_OUTW) { s = s0; off = W_INW;  }
    else if (i < W_L1W)  { s = s1; off = W_OUTW; }
    else if (i < W_L2W)  { s = s2; off = W_L1W;  }
    else if (i < W_FINW) { s = s3; off = W_L2W;  }
    else                 { s = s4; off = W_FINW; }
    __half h, l;
    h2split(s[i - off], h, l);
    g_w_hi[i] = h;
    g_w_lo[i] = l;
}

// ---------------- per-voxel LN + positional feature -> half hi/lo ----------
__global__ void kf_kernel(const float* __restrict__ vf,
                          const float* __restrict__ vc,
                          const float* __restrict__ g1,
                          const float* __restrict__ b1,
                          const float* __restrict__ kpw,
                          const float* __restrict__ kpb)
{
    int v    = blockIdx.x * 8 + (threadIdx.x >> 5);
    int lane = threadIdx.x & 31;
    if (v >= NVOX) return;

    float4 x = ((const float4*)(vf + (size_t)v * C))[lane];
    float s = x.x + x.y + x.z + x.w;
    float q = x.x * x.x + x.y * x.y + x.z * x.z + x.w * x.w;
#pragma unroll
    for (int o = 16; o; o >>= 1) {
        s += __shfl_xor_sync(0xffffffffu, s, o);
        q += __shfl_xor_sync(0xffffffffu, q, o);
    }
    float m   = s * (1.0f / 128.0f);
    float var = q * (1.0f / 128.0f) - m * m;
    float r   = rsqrtf(var + 1e-5f);

    float cx = vc[v * 3 + 0], cy = vc[v * 3 + 1], cz = vc[v * 3 + 2];

    const float* xv = &x.x;
#pragma unroll
    for (int j = 0; j < 4; j++) {
        int c = lane * 4 + j;
        float y  = (xv[j] - m) * r * g1[c] + b1[c];
        float kp = fmaxf(kpw[c * 3 + 0] * cx + kpw[c * 3 + 1] * cy +
                         kpw[c * 3 + 2] * cz + kpb[c], 0.0f);
        __half h, l;
        h2split(y + kp, h, l);
        g_kf_hi[v * C + c] = h;
        g_kf_lo[v * C + c] = l;
    }
}

// ---------------- row LayerNorm (norm2) -> half hi/lo ----------------
__global__ void ln_kernel(const float* __restrict__ in,
                          const float* __restrict__ g,
                          const float* __restrict__ b)
{
    int r    = blockIdx.x * 8 + (threadIdx.x >> 5);
    int lane = threadIdx.x & 31;

    float4 x = ((const float4*)(in + (size_t)r * C))[lane];
    float s = x.x + x.y + x.z + x.w;
    float q = x.x * x.x + x.y * x.y + x.z * x.z + x.w * x.w;
#pragma unroll
    for (int o = 16; o; o >>= 1) {
        s += __shfl_xor_sync(0xffffffffu, s, o);
        q += __shfl_xor_sync(0xffffffffu, q, o);
    }
    float m   = s * (1.0f / 128.0f);
    float var = q * (1.0f / 128.0f) - m * m;
    float rs  = rsqrtf(var + 1e-5f);

    const float* xv = &x.x;
#pragma unroll
    for (int j = 0; j < 4; j++) {
        int c = lane * 4 + j;
        __half h, l;
        h2split((xv[j] - m) * rs * g[c] + b[c], h, l);
        g_hn_hi[r * C + c] = h;
        g_hn_lo[r * C + c] = l;
    }
}

// ---------------- query positional feature -> half hi/lo ----------------
__global__ void qfeat_kernel(const float* __restrict__ qc,
                             const float* __restrict__ qpw,
                             const float* __restrict__ qpb)
{
    int t = blockIdx.x * 256 + threadIdx.x;
    int n = t >> 7, c = t & 127;
    float x = qc[n * 3 + 0], y = qc[n * 3 + 1], z = qc[n * 3 + 2];
    float v = fmaxf(qpw[c * 3 + 0] * x + qpw[c * 3 + 1] * y +
                    qpw[c * 3 + 2] * z + qpb[c], 0.0f);
    __half h, l;
    h2split(v, h, l);
    g_qf_hi[t] = h;
    g_qf_lo[t] = l;
}

// ---------------- tensor-core GEMM (fp16 hi/lo x3, ldmatrix) ----------------
// out[M,N] = A[M,Kd] @ W[N,Kd]^T (+bias)(+res)(relu)
// CTA 64x64, 4 warps of 32x32, BK=32.
// flags: 1=relu, 2=res, 4=half out, 8=f32 out, 16=half hi/lo out
__global__ __launch_bounds__(128)
void mma_gemm(const __half* __restrict__ Ahi, const __half* __restrict__ Alo,
              const __half* __restrict__ Whi, const __half* __restrict__ Wlo,
              const float* __restrict__ bias, const float* __restrict__ res,
              float* __restrict__ out32, __half* __restrict__ outh,
              __half* __restrict__ ohi, __half* __restrict__ olo,
              int N, int Kd, int flags)
{
    // [plane][row 0..63][4 swizzled 8-half chunks]
    __shared__ __align__(16) __half sA[2][64 * 32];
    __shared__ __align__(16) __half sB[2][64 * 32];

    const int tid  = threadIdx.x;
    const int m0   = blockIdx.x * 64;
    const int n0   = blockIdx.y * 64;
    const int lane = tid & 31;
    const int g    = lane >> 2;
    const int tig  = lane & 3;
    const int wm   = tid >> 6;
    const int wn   = (tid >> 5) & 1;

    // ---- loader mapping: slot s -> row=s>>2, chunk c=s&3 ; slots tid, tid+128
    const int lr0 = tid >> 2, lc = tid & 3;
    const int lr1 = lr0 + 32;
    const int so0 = lr0 * 32 + ((lc ^ skey(lr0)) << 3);   // half offsets
    const int so1 = lr1 * 32 + ((lc ^ skey(lr1)) << 3);

    // ---- loop-invariant ldmatrix addresses ----
    const int mat = lane >> 3, l8 = lane & 7;
    uint32_t baseA[2] = { (uint32_t)__cvta_generic_to_shared(sA[0]),
                          (uint32_t)__cvta_generic_to_shared(sA[1]) };
    uint32_t baseB[2] = { (uint32_t)__cvta_generic_to_shared(sB[0]),
                          (uint32_t)__cvta_generic_to_shared(sB[1]) };
    uint32_t adA[2][2][2], adB[2][2][2];   // [plane][mt|np][kc16]
#pragma unroll
    for (int pl = 0; pl < 2; pl++)
#pragma unroll
        for (int i = 0; i < 2; i++)
#pragma unroll
            for (int kh = 0; kh < 2; kh++) {
                int ra = wm * 32 + i * 16 + (mat & 1) * 8 + l8;
                int ca = kh * 2 + (mat >> 1);
                adA[pl][i][kh] = baseA[pl] + (ra * 32 + ((ca ^ skey(ra)) << 3)) * 2;
                int rb = wn * 32 + i * 16 + (mat >> 1) * 8 + l8;
                int cb = kh * 2 + (mat & 1);
                adB[pl][i][kh] = baseB[pl] + (rb * 32 + ((cb ^ skey(rb)) << 3)) * 2;
            }

    float acc[2][4][4];
#pragma unroll
    for (int t = 0; t < 2; t++)
#pragma unroll
        for (int j = 0; j < 4; j++)
#pragma unroll
            for (int e = 0; e < 4; e++) acc[t][j][e] = 0.0f;

    // ---- prefetch first k-chunk ----
    size_t a0 = (size_t)(m0 + lr0) * Kd + lc * 8;
    size_t a1 = (size_t)(m0 + lr1) * Kd + lc * 8;
    size_t b0 = (size_t)(n0 + lr0) * Kd + lc * 8;
    size_t b1 = (size_t)(n0 + lr1) * Kd + lc * 8;
    uint4 pah0 = *(const uint4*)(Ahi + a0), pah1 = *(const uint4*)(Ahi + a1);
    uint4 pal0 = *(const uint4*)(Alo + a0), pal1 = *(const uint4*)(Alo + a1);
    uint4 pbh0 = *(const uint4*)(Whi + b0), pbh1 = *(const uint4*)(Whi + b1);
    uint4 pbl0 = *(const uint4*)(Wlo + b0), pbl1 = *(const uint4*)(Wlo + b1);

    for (int kc = 0; kc < Kd; kc += 32) {
        *(uint4*)(sA[0] + so0) = pah0;  *(uint4*)(sA[0] + so1) = pah1;
        *(uint4*)(sA[1] + so0) = pal0;  *(uint4*)(sA[1] + so1) = pal1;
        *(uint4*)(sB[0] + so0) = pbh0;  *(uint4*)(sB[0] + so1) = pbh1;
        *(uint4*)(sB[1] + so0) = pbl0;  *(uint4*)(sB[1] + so1) = pbl1;
        __syncthreads();

        const bool more = (kc + 32) < Kd;
        if (more) {
            size_t o = kc + 32;
            pah0 = *(const uint4*)(Ahi + a0 + o);  pah1 = *(const uint4*)(Ahi + a1 + o);
            pal0 = *(const uint4*)(Alo + a0 + o);  pal1 = *(const uint4*)(Alo + a1 + o);
            pbh0 = *(const uint4*)(Whi + b0 + o);  pbh1 = *(const uint4*)(Whi + b1 + o);
            pbl0 = *(const uint4*)(Wlo + b0 + o);  pbl1 = *(const uint4*)(Wlo + b1 + o);
        }

#pragma unroll
        for (int kh = 0; kh < 2; kh++) {
            uint32_t ah[2][4], al[2][4], bh[2][4], bl[2][4];
#pragma unroll
            for (int i = 0; i < 2; i++) {
                ldsm4(ah[i], adA[0][i][kh]);
                ldsm4(al[i], adA[1][i][kh]);
                ldsm4(bh[i], adB[0][i][kh]);
                ldsm4(bl[i], adB[1][i][kh]);
            }
#pragma unroll
            for (int t = 0; t < 2; t++)
#pragma unroll
                for (int j = 0; j < 4; j++) {
                    const uint32_t* bhp = &bh[j >> 1][(j & 1) * 2];
                    const uint32_t* blp = &bl[j >> 1][(j & 1) * 2];
                    mma16(acc[t][j], ah[t], bhp);
                    mma16(acc[t][j], ah[t], blp);
                    mma16(acc[t][j], al[t], bhp);
                }
        }
        __syncthreads();
    }

    // ---- epilogue ----
#pragma unroll
    for (int t = 0; t < 2; t++) {
#pragma unroll
        for (int j = 0; j < 4; j++) {
            int row0 = m0 + wm * 32 + t * 16 + g;
            int col  = n0 + wn * 32 + j * 8 + 2 * tig;
            float2 bi = *(const float2*)(bias + col);
#pragma unroll
            for (int h2 = 0; h2 < 2; h2++) {
                int row = row0 + h2 * 8;
                float x0 = acc[t][j][h2 * 2 + 0] + bi.x;
                float x1 = acc[t][j][h2 * 2 + 1] + bi.y;
                size_t o = (size_t)row * N + col;
                if (flags & 2) {
                    float2 r2 = *(const float2*)(res + o);
                    x0 += r2.x; x1 += r2.y;
                }
                if (flags & 1) { x0 = fmaxf(x0, 0.0f); x1 = fmaxf(x1, 0.0f); }
                if (flags & 8)  *(float2*)(out32 + o) = make_float2(x0, x1);
                if (flags & 4)  *(__half2*)(outh + o) = __floats2half2_rn(x0, x1);
                if (flags & 16) {
                    __half h0, l0, h1, l1;
                    h2split(x0, h0, l0);
                    h2split(x1, h1, l1);
                    ohi[o] = h0; ohi[o + 1] = h1;
                    olo[o] = l0; olo[o + 1] = l1;
                }
            }
        }
    }
}

// ---------------- attention: one block per query, 128 threads ----------------
__global__ __launch_bounds__(128)
void attn_kernel(const int* __restrict__ kidx)
{
    __shared__ int   idx_s[KK];
    __shared__ float p_s[NH][KK];
    __shared__ __align__(16) __half kv_s[KK * KVROW];

    const int n = blockIdx.x;
    const int t = threadIdx.x;
    const int h = t >> 4, l16 = t & 15;

    if (t < KK) idx_s[t] = kidx[n * KK + t];
    __syncthreads();

    // prefetch this thread's 6 K head-slices (32B each) from L2
    uint4 kreg[6][2];
    int vidx[6];
#pragma unroll
    for (int m = 0; m < 6; m++) {
        int v = idx_s[l16 + m * 16];
        vidx[m] = v;
        if (v >= 0) {
            const uint4* p = (const uint4*)(g_KVh + (size_t)v * 256 + h * 16);
            kreg[m][0] = p[0];
            kreg[m][1] = p[1];
        }
    }

    float qreg[16];
    {
        const float* qp = g_q + (size_t)n * C + h * 16;
#pragma unroll
        for (int d = 0; d < 16; d++) qreg[d] = qp[d];
    }

    float sc[6];
#pragma unroll
    for (int m = 0; m < 6; m++) {
        const __half2* kp = (const __half2*)&kreg[m][0];
        float s = 0.0f;
#pragma unroll
        for (int d = 0; d < 8; d++) {
            float2 kv2 = __half22float2(kp[d]);
            s += qreg[2 * d] * kv2.x + qreg[2 * d + 1] * kv2.y;
        }
        sc[m] = s * 0.25f;
    }

    float mx = -1e30f;
#pragma unroll
    for (int m = 0; m < 6; m++)
        if (vidx[m] >= 0) mx = fmaxf(mx, sc[m]);
#pragma unroll
    for (int o = 8; o; o >>= 1)
        mx = fmaxf(mx, __shfl_xor_sync(0xffffffffu, mx, o, 16));

    float p[6];
    float sum = 0.0f;
#pragma unroll
    for (int m = 0; m < 6; m++) {
        p[m] = (vidx[m] >= 0) ? __expf(sc[m] - mx) : 0.0f;
        sum += p[m];
    }
#pragma unroll
    for (int o = 8; o; o >>= 1)
        sum += __shfl_xor_sync(0xffffffffu, sum, o, 16);
    const float inv = 1.0f / sum;
#pragma unroll
    for (int m = 0; m < 6; m++) p_s[h][l16 + m * 16] = p[m] * inv;

    // stage V rows (second 256B half of each KV row)
    const int rg = t >> 4;
    const int pp = t & 15;
#pragma unroll
    for (int i = 0; i < 12; i++) {
        int k = i * 8 + rg;
        int v = idx_s[k];
        uint4 d = make_uint4(0, 0, 0, 0);
        if (v >= 0) d = ((const uint4*)(g_KVh + (size_t)v * 256))[16 + pp];
        *(uint4*)(&kv_s[k * KVROW + pp * 8]) = d;
    }
    __syncthreads();

    float acc = 0.0f;
#pragma unroll 8
    for (int k = 0; k < KK; k++)
        acc += p_s[h][k] * __half2float(kv_s[k * KVROW + t]);

    __half hh, ll;
    h2split(acc, hh, ll);
    g_ctx_hi[n * C + t] = hh;
    g_ctx_lo[n * C + t] = ll;
}

// ---------------- host launch ----------------
extern "C" void kernel_launch(void* const* d_in, const int* in_sizes, int n_in,
                              void* d_out, int out_size)
{
    const float* vf   = (const float*)d_in[0];
    const float* vc   = (const float*)d_in[1];
    const float* qc   = (const float*)d_in[2];
    const int*   kidx = (const int*)  d_in[3];
    const float* n1g  = (const float*)d_in[4];
    const float* n1b  = (const float*)d_in[5];
    const float* qpw  = (const float*)d_in[6];
    const float* qpb  = (const float*)d_in[7];
    const float* kpw  = (const float*)d_in[8];
    const float* kpb  = (const float*)d_in[9];
    const float* inw  = (const float*)d_in[10];
    const float* inb  = (const float*)d_in[11];
    const float* outw = (const float*)d_in[12];
    const float* outb = (const float*)d_in[13];
    const float* n2g  = (const float*)d_in[14];
    const float* n2b  = (const float*)d_in[15];
    const float* l1w  = (const float*)d_in[16];
    const float* l1b  = (const float*)d_in[17];
    const float* l2w  = (const float*)d_in[18];
    const float* l2b  = (const float*)d_in[19];
    const float* fw   = (const float*)d_in[20];
    const float* fb   = (const float*)d_in[21];
    float* out = (float*)d_out;

    __half *p_kf_hi, *p_kf_lo, *p_qf_hi, *p_qf_lo, *p_ctx_hi, *p_ctx_lo;
    __half *p_hn_hi, *p_hn_lo, *p_a1_hi, *p_a1_lo, *p_x_hi, *p_x_lo;
    __half *p_w_hi, *p_w_lo, *p_KVh;
    float *p_q, *p_att;
    cudaGetSymbolAddress((void**)&p_kf_hi,  g_kf_hi);
    cudaGetSymbolAddress((void**)&p_kf_lo,  g_kf_lo);
    cudaGetSymbolAddress((void**)&p_KVh,    g_KVh);
    cudaGetSymbolAddress((void**)&p_qf_hi,  g_qf_hi);
    cudaGetSymbolAddress((void**)&p_qf_lo,  g_qf_lo);
    cudaGetSymbolAddress((void**)&p_q,      g_q);
    cudaGetSymbolAddress((void**)&p_ctx_hi, g_ctx_hi);
    cudaGetSymbolAddress((void**)&p_ctx_lo, g_ctx_lo);
    cudaGetSymbolAddress((void**)&p_att,    g_att);
    cudaGetSymbolAddress((void**)&p_hn_hi,  g_hn_hi);
    cudaGetSymbolAddress((void**)&p_hn_lo,  g_hn_lo);
    cudaGetSymbolAddress((void**)&p_a1_hi,  g_a1_hi);
    cudaGetSymbolAddress((void**)&p_a1_lo,  g_a1_lo);
    cudaGetSymbolAddress((void**)&p_x_hi,   g_x_hi);
    cudaGetSymbolAddress((void**)&p_x_lo,   g_x_lo);
    cudaGetSymbolAddress((void**)&p_w_hi,   g_w_hi);
    cudaGetSymbolAddress((void**)&p_w_lo,   g_w_lo);

    // 0) weights -> fp16 hi/lo
    wsplit_kernel<<<(W_TOT + 255) / 256, 256>>>(inw, outw, l1w, l2w, fw);

    // 1) per-voxel LN + key positional feature
    kf_kernel<<<NVOX / 8, 256>>>(vf, vc, n1g, n1b, kpw, kpb);

    // 2) query positional feature
    qfeat_kernel<<<(NQ * C) / 256, 256>>>(qc, qpw, qpb);

    // 3) per-voxel K|V projection -> fp16 [NVOX,256]  (profiled launch)
    mma_gemm<<<dim3(NVOX / 64, 4), 128>>>(
        p_kf_hi, p_kf_lo, p_w_hi + W_INW + 128 * 128, p_w_lo + W_INW + 128 * 128,
        inb + 128, nullptr, nullptr, p_KVh, nullptr, nullptr, 256, 128, 4);

    // 4) q projection -> fp32
    mma_gemm<<<dim3(NQ / 64, 2), 128>>>(
        p_qf_hi, p_qf_lo, p_w_hi + W_INW, p_w_lo + W_INW,
        inb, nullptr, p_q, nullptr, nullptr, nullptr, 128, 128, 8);

    // 5) sparse attention -> ctx hi/lo
    attn_kernel<<<NQ, 128>>>(kidx);

    // 6) output projection -> attend fp32
    mma_gemm<<<dim3(NQ / 64, 2), 128>>>(
        p_ctx_hi, p_ctx_lo, p_w_hi + W_OUTW, p_w_lo + W_OUTW,
        outb, nullptr, p_att, nullptr, nullptr, nullptr, 128, 128, 8);

    // 7) norm2 -> hn hi/lo
    ln_kernel<<<NQ / 8, 256>>>(p_att, n2g, n2b);

    // 8) FFN up (relu) -> a1 hi/lo
    mma_gemm<<<dim3(NQ / 64, 4), 128>>>(
        p_hn_hi, p_hn_lo, p_w_hi + W_L1W, p_w_lo + W_L1W,
        l1b, nullptr, nullptr, nullptr, p_a1_hi, p_a1_lo, 256, 128, 16 | 1);

    // 9) FFN down + residual(attend) -> x hi/lo
    mma_gemm<<<dim3(NQ / 64, 2), 128>>>(
        p_a1_hi, p_a1_lo, p_w_hi + W_L2W, p_w_lo + W_L2W,
        l2b, p_att, nullptr, nullptr, p_x_hi, p_x_lo, 128, 256, 16 | 2);

    // 10) final projection + relu -> output fp32
    mma_gemm<<<dim3(NQ / 64, 2), 128>>>(
        p_x_hi, p_x_lo, p_w_hi + W_FINW, p_w_lo + W_FINW,
        fb, nullptr, out, nullptr, nullptr, nullptr, 128, 128, 8 | 1);
}

// round 8
// speedup vs baseline: 2.2708x; 1.1516x over previous
#include <cuda_runtime.h>
#include <cuda_fp16.h>
#include <math.h>
#include <stdint.h>

#define NVOX 40000
#define NQ   8192
#define KK   96
#define C    128
#define FF   256
#define NH   8
#define KVROW 136

// weight split buffer offsets (halfs)
#define W_INW  0
#define W_OUTW 49152
#define W_L1W  65536
#define W_L2W  98304
#define W_FINW 131072
#define W_TOT  147456

// ---------------- scratch (device globals; no allocation) ----------------
__device__ __half g_w_hi[W_TOT],     g_w_lo[W_TOT];
__device__ __half g_kf_hi[NVOX * C];
__device__ __half g_KVh[NVOX * 2 * C];
__device__ __half g_qf_hi[NQ * C];
__device__ float  g_q[NQ * C];
__device__ __half g_ctx_hi[NQ * C],  g_ctx_lo[NQ * C];
__device__ float  g_att[NQ * C];
__device__ __half g_hn_hi[NQ * C],   g_hn_lo[NQ * C];
__device__ __half g_a1_hi[NQ * FF],  g_a1_lo[NQ * FF];
__device__ __half g_x_hi[NQ * C],    g_x_lo[NQ * C];

// ---------------- helpers ----------------
__device__ __forceinline__ void h2split(float x, __half& h, __half& l) {
    h = __float2half(x);
    l = __float2half(x - __half2float(h));
}

__device__ __forceinline__ int skey(int r) { return (r ^ (r >> 2)) & 3; }

__device__ __forceinline__ void ldsm4(uint32_t* r, uint32_t addr) {
    asm volatile("ldmatrix.sync.aligned.m8n8.x4.shared.b16 {%0,%1,%2,%3}, [%4];"
                 : "=r"(r[0]), "=r"(r[1]), "=r"(r[2]), "=r"(r[3]) : "r"(addr));
}

__device__ __forceinline__ void mma16(float* d, const uint32_t* a, const uint32_t* b) {
    asm volatile(
        "mma.sync.aligned.m16n8k16.row.col.f32.f16.f16.f32 "
        "{%0,%1,%2,%3}, {%4,%5,%6,%7}, {%8,%9}, {%0,%1,%2,%3};"
        : "+f"(d[0]), "+f"(d[1]), "+f"(d[2]), "+f"(d[3])
        : "r"(a[0]), "r"(a[1]), "r"(a[2]), "r"(a[3]), "r"(b[0]), "r"(b[1]));
}

__device__ __forceinline__ void cpa16(uint32_t s, const void* g) {
    asm volatile("cp.async.cg.shared.global [%0], [%1], 16;" :: "r"(s), "l"(g));
}
__device__ __forceinline__ void cpa_commit() {
    asm volatile("cp.async.commit_group;");
}
template <int N>
__device__ __forceinline__ void cpa_wait() {
    asm volatile("cp.async.wait_group %0;" :: "n"(N));
}

// ---------------- weight hi/lo split ----------------
__global__ void wsplit_kernel(const float* __restrict__ s0,
                              const float* __restrict__ s1,
                              const float* __restrict__ s2,
                              const float* __restrict__ s3,
                              const float* __restrict__ s4)
{
    int i = blockIdx.x * 256 + threadIdx.x;
    if (i >= W_TOT) return;
    const float* s; int off;
    if      (i < W_OUTW) { s = s0; off = W_INW;  }
    else if (i < W_L1W)  { s = s1; off = W_OUTW; }
    else if (i < W_L2W)  { s = s2; off = W_L1W;  }
    else if (i < W_FINW) { s = s3; off = W_L2W;  }
    else                 { s = s4; off = W_FINW; }
    __half h, l;
    h2split(s[i - off], h, l);
    g_w_hi[i] = h;
    g_w_lo[i] = l;
}

// ---------------- per-voxel LN + positional feature -> half ----------------
__global__ void kf_kernel(const float* __restrict__ vf,
                          const float* __restrict__ vc,
                          const float* __restrict__ g1,
                          const float* __restrict__ b1,
                          const float* __restrict__ kpw,
                          const float* __restrict__ kpb)
{
    int v    = blockIdx.x * 8 + (threadIdx.x >> 5);
    int lane = threadIdx.x & 31;
    if (v >= NVOX) return;

    float4 x = ((const float4*)(vf + (size_t)v * C))[lane];
    float s = x.x + x.y + x.z + x.w;
    float q = x.x * x.x + x.y * x.y + x.z * x.z + x.w * x.w;
#pragma unroll
    for (int o = 16; o; o >>= 1) {
        s += __shfl_xor_sync(0xffffffffu, s, o);
        q += __shfl_xor_sync(0xffffffffu, q, o);
    }
    float m   = s * (1.0f / 128.0f);
    float var = q * (1.0f / 128.0f) - m * m;
    float r   = rsqrtf(var + 1e-5f);

    float cx = vc[v * 3 + 0], cy = vc[v * 3 + 1], cz = vc[v * 3 + 2];

    const float* xv = &x.x;
#pragma unroll
    for (int j = 0; j < 4; j++) {
        int c = lane * 4 + j;
        float y  = (xv[j] - m) * r * g1[c] + b1[c];
        float kp = fmaxf(kpw[c * 3 + 0] * cx + kpw[c * 3 + 1] * cy +
                         kpw[c * 3 + 2] * cz + kpb[c], 0.0f);
        g_kf_hi[v * C + c] = __float2half(y + kp);
    }
}

// ---------------- row LayerNorm (norm2) -> half hi/lo ----------------
__global__ void ln_kernel(const float* __restrict__ in,
                          const float* __restrict__ g,
                          const float* __restrict__ b)
{
    int r    = blockIdx.x * 8 + (threadIdx.x >> 5);
    int lane = threadIdx.x & 31;

    float4 x = ((const float4*)(in + (size_t)r * C))[lane];
    float s = x.x + x.y + x.z + x.w;
    float q = x.x * x.x + x.y * x.y + x.z * x.z + x.w * x.w;
#pragma unroll
    for (int o = 16; o; o >>= 1) {
        s += __shfl_xor_sync(0xffffffffu, s, o);
        q += __shfl_xor_sync(0xffffffffu, q, o);
    }
    float m   = s * (1.0f / 128.0f);
    float var = q * (1.0f / 128.0f) - m * m;
    float rs  = rsqrtf(var + 1e-5f);

    const float* xv = &x.x;
#pragma unroll
    for (int j = 0; j < 4; j++) {
        int c = lane * 4 + j;
        __half h, l;
        h2split((xv[j] - m) * rs * g[c] + b[c], h, l);
        g_hn_hi[r * C + c] = h;
        g_hn_lo[r * C + c] = l;
    }
}

// ---------------- query positional feature -> half ----------------
__global__ void qfeat_kernel(const float* __restrict__ qc,
                             const float* __restrict__ qpw,
                             const float* __restrict__ qpb)
{
    int t = blockIdx.x * 256 + threadIdx.x;
    int n = t >> 7, c = t & 127;
    float x = qc[n * 3 + 0], y = qc[n * 3 + 1], z = qc[n * 3 + 2];
    float v = fmaxf(qpw[c * 3 + 0] * x + qpw[c * 3 + 1] * y +
                    qpw[c * 3 + 2] * z + qpb[c], 0.0f);
    g_qf_hi[t] = __float2half(v);
}

// ---------------- tensor-core GEMM (fp16, PL=1 single / PL=2 hi-lo x3) -----
// out[M,N] = A[M,Kd] @ W[N,Kd]^T (+bias)(+res)(relu)
// CTA 64x64, 4 warps of 32x32, BK=32, cp.async double-buffered.
// flags: 1=relu, 2=res, 4=half out, 8=f32 out, 16=half hi/lo out
template <int PL>
__global__ __launch_bounds__(128)
void mma_gemm(const __half* __restrict__ Ahi, const __half* __restrict__ Alo,
              const __half* __restrict__ Whi, const __half* __restrict__ Wlo,
              const float* __restrict__ bias, const float* __restrict__ res,
              float* __restrict__ out32, __half* __restrict__ outh,
              __half* __restrict__ ohi, __half* __restrict__ olo,
              int N, int Kd, int flags)
{
    __shared__ __align__(16) __half sA[2][PL][64 * 32];
    __shared__ __align__(16) __half sB[2][PL][64 * 32];

    const int tid  = threadIdx.x;
    const int m0   = blockIdx.x * 64;
    const int n0   = blockIdx.y * 64;
    const int lane = tid & 31;
    const int g    = lane >> 2;
    const int tig  = lane & 3;
    const int wm   = tid >> 6;
    const int wn   = (tid >> 5) & 1;

    // loader: slot tid -> (row=tid>>2, chunk=tid&3), plus row+32
    const int lr0 = tid >> 2, lc = tid & 3, lr1 = lr0 + 32;
    const int so0 = (lr0 * 32 + ((lc ^ skey(lr0)) << 3)) * 2;  // byte offset
    const int so1 = (lr1 * 32 + ((lc ^ skey(lr1)) << 3)) * 2;

    uint32_t bA[2][PL], bB[2][PL];
#pragma unroll
    for (int bu = 0; bu < 2; bu++)
#pragma unroll
        for (int pl = 0; pl < PL; pl++) {
            bA[bu][pl] = (uint32_t)__cvta_generic_to_shared(sA[bu][pl]);
            bB[bu][pl] = (uint32_t)__cvta_generic_to_shared(sB[bu][pl]);
        }

    // ldmatrix offsets within a 64x32 tile (bytes)
    const int mat = lane >> 3, l8 = lane & 7;
    int offA[2][2], offB[2][2];
#pragma unroll
    for (int i = 0; i < 2; i++)
#pragma unroll
        for (int kh = 0; kh < 2; kh++) {
            int ra = wm * 32 + i * 16 + (mat & 1) * 8 + l8;
            int ca = kh * 2 + (mat >> 1);
            offA[i][kh] = (ra * 32 + ((ca ^ skey(ra)) << 3)) * 2;
            int rb = wn * 32 + i * 16 + (mat >> 1) * 8 + l8;
            int cb = kh * 2 + (mat & 1);
            offB[i][kh] = (rb * 32 + ((cb ^ skey(rb)) << 3)) * 2;
        }

    const __half* Ap[2] = { Ahi, Alo };
    const __half* Wp[2] = { Whi, Wlo };

    float acc[2][4][4];
#pragma unroll
    for (int t = 0; t < 2; t++)
#pragma unroll
        for (int j = 0; j < 4; j++)
#pragma unroll
            for (int e = 0; e < 4; e++) acc[t][j][e] = 0.0f;

    // stage chunk 0 into buffer 0
#pragma unroll
    for (int pl = 0; pl < PL; pl++) {
        cpa16(bA[0][pl] + so0, Ap[pl] + (size_t)(m0 + lr0) * Kd + lc * 8);
        cpa16(bA[0][pl] + so1, Ap[pl] + (size_t)(m0 + lr1) * Kd + lc * 8);
        cpa16(bB[0][pl] + so0, Wp[pl] + (size_t)(n0 + lr0) * Kd + lc * 8);
        cpa16(bB[0][pl] + so1, Wp[pl] + (size_t)(n0 + lr1) * Kd + lc * 8);
    }
    cpa_commit();

    int buf = 0;
    for (int kc = 0; kc < Kd; kc += 32) {
        const bool more = (kc + 32) < Kd;
        if (more) {
            int nb = buf ^ 1;
            int ko = kc + 32;
#pragma unroll
            for (int pl = 0; pl < PL; pl++) {
                cpa16(bA[nb][pl] + so0, Ap[pl] + (size_t)(m0 + lr0) * Kd + ko + lc * 8);
                cpa16(bA[nb][pl] + so1, Ap[pl] + (size_t)(m0 + lr1) * Kd + ko + lc * 8);
                cpa16(bB[nb][pl] + so0, Wp[pl] + (size_t)(n0 + lr0) * Kd + ko + lc * 8);
                cpa16(bB[nb][pl] + so1, Wp[pl] + (size_t)(n0 + lr1) * Kd + ko + lc * 8);
            }
            cpa_commit();
            cpa_wait<1>();
        } else {
            cpa_wait<0>();
        }
        __syncthreads();

#pragma unroll
        for (int kh = 0; kh < 2; kh++) {
            uint32_t ah[2][4], bh[2][4];
            uint32_t al[2][4], bl[2][4];
#pragma unroll
            for (int i = 0; i < 2; i++) {
                ldsm4(ah[i], bA[buf][0] + offA[i][kh]);
                ldsm4(bh[i], bB[buf][0] + offB[i][kh]);
                if (PL == 2) {
                    ldsm4(al[i], bA[buf][1] + offA[i][kh]);
                    ldsm4(bl[i], bB[buf][1] + offB[i][kh]);
                }
            }
#pragma unroll
            for (int t = 0; t < 2; t++)
#pragma unroll
                for (int j = 0; j < 4; j++) {
                    const uint32_t* bhp = &bh[j >> 1][(j & 1) * 2];
                    mma16(acc[t][j], ah[t], bhp);
                    if (PL == 2) {
                        const uint32_t* blp = &bl[j >> 1][(j & 1) * 2];
                        mma16(acc[t][j], ah[t], blp);
                        mma16(acc[t][j], al[t], bhp);
                    }
                }
        }
        __syncthreads();
        buf ^= 1;
    }

    // ---- epilogue ----
#pragma unroll
    for (int t = 0; t < 2; t++) {
#pragma unroll
        for (int j = 0; j < 4; j++) {
            int row0 = m0 + wm * 32 + t * 16 + g;
            int col  = n0 + wn * 32 + j * 8 + 2 * tig;
            float2 bi = *(const float2*)(bias + col);
#pragma unroll
            for (int h2 = 0; h2 < 2; h2++) {
                int row = row0 + h2 * 8;
                float x0 = acc[t][j][h2 * 2 + 0] + bi.x;
                float x1 = acc[t][j][h2 * 2 + 1] + bi.y;
                size_t o = (size_t)row * N + col;
                if (flags & 2) {
                    float2 r2 = *(const float2*)(res + o);
                    x0 += r2.x; x1 += r2.y;
                }
                if (flags & 1) { x0 = fmaxf(x0, 0.0f); x1 = fmaxf(x1, 0.0f); }
                if (flags & 8)  *(float2*)(out32 + o) = make_float2(x0, x1);
                if (flags & 4)  *(__half2*)(outh + o) = __floats2half2_rn(x0, x1);
                if (flags & 16) {
                    __half h0, l0, h1, l1;
                    h2split(x0, h0, l0);
                    h2split(x1, h1, l1);
                    ohi[o] = h0; ohi[o + 1] = h1;
                    olo[o] = l0; olo[o + 1] = l1;
                }
            }
        }
    }
}

// ---------------- attention: one block per query, 128 threads ----------------
__global__ __launch_bounds__(128)
void attn_kernel(const int* __restrict__ kidx)
{
    __shared__ int   idx_s[KK];
    __shared__ float p_s[NH][KK];
    __shared__ __align__(16) __half kv_s[KK * KVROW];

    const int n = blockIdx.x;
    const int t = threadIdx.x;
    const int h = t >> 4, l16 = t & 15;

    if (t < KK) idx_s[t] = kidx[n * KK + t];
    __syncthreads();

    uint4 kreg[6][2];
    int vidx[6];
#pragma unroll
    for (int m = 0; m < 6; m++) {
        int v = idx_s[l16 + m * 16];
        vidx[m] = v;
        if (v >= 0) {
            const uint4* p = (const uint4*)(g_KVh + (size_t)v * 256 + h * 16);
            kreg[m][0] = p[0];
            kreg[m][1] = p[1];
        }
    }

    float qreg[16];
    {
        const float* qp = g_q + (size_t)n * C + h * 16;
#pragma unroll
        for (int d = 0; d < 16; d++) qreg[d] = qp[d];
    }

    float sc[6];
#pragma unroll
    for (int m = 0; m < 6; m++) {
        const __half2* kp = (const __half2*)&kreg[m][0];
        float s = 0.0f;
#pragma unroll
        for (int d = 0; d < 8; d++) {
            float2 kv2 = __half22float2(kp[d]);
            s += qreg[2 * d] * kv2.x + qreg[2 * d + 1] * kv2.y;
        }
        sc[m] = s * 0.25f;
    }

    float mx = -1e30f;
#pragma unroll
    for (int m = 0; m < 6; m++)
        if (vidx[m] >= 0) mx = fmaxf(mx, sc[m]);
#pragma unroll
    for (int o = 8; o; o >>= 1)
        mx = fmaxf(mx, __shfl_xor_sync(0xffffffffu, mx, o, 16));

    float p[6];
    float sum = 0.0f;
#pragma unroll
    for (int m = 0; m < 6; m++) {
        p[m] = (vidx[m] >= 0) ? __expf(sc[m] - mx) : 0.0f;
        sum += p[m];
    }
#pragma unroll
    for (int o = 8; o; o >>= 1)
        sum += __shfl_xor_sync(0xffffffffu, sum, o, 16);
    const float inv = 1.0f / sum;
#pragma unroll
    for (int m = 0; m < 6; m++) p_s[h][l16 + m * 16] = p[m] * inv;

    const int rg = t >> 4;
    const int pp = t & 15;
#pragma unroll
    for (int i = 0; i < 12; i++) {
        int k = i * 8 + rg;
        int v = idx_s[k];
        uint4 d = make_uint4(0, 0, 0, 0);
        if (v >= 0) d = ((const uint4*)(g_KVh + (size_t)v * 256))[16 + pp];
        *(uint4*)(&kv_s[k * KVROW + pp * 8]) = d;
    }
    __syncthreads();

    float acc = 0.0f;
#pragma unroll 8
    for (int k = 0; k < KK; k++)
        acc += p_s[h][k] * __half2float(kv_s[k * KVROW + t]);

    __half hh, ll;
    h2split(acc, hh, ll);
    g_ctx_hi[n * C + t] = hh;
    g_ctx_lo[n * C + t] = ll;
}

// ---------------- host launch ----------------
extern "C" void kernel_launch(void* const* d_in, const int* in_sizes, int n_in,
                              void* d_out, int out_size)
{
    const float* vf   = (const float*)d_in[0];
    const float* vc   = (const float*)d_in[1];
    const float* qc   = (const float*)d_in[2];
    const int*   kidx = (const int*)  d_in[3];
    const float* n1g  = (const float*)d_in[4];
    const float* n1b  = (const float*)d_in[5];
    const float* qpw  = (const float*)d_in[6];
    const float* qpb  = (const float*)d_in[7];
    const float* kpw  = (const float*)d_in[8];
    const float* kpb  = (const float*)d_in[9];
    const float* inw  = (const float*)d_in[10];
    const float* inb  = (const float*)d_in[11];
    const float* outw = (const float*)d_in[12];
    const float* outb = (const float*)d_in[13];
    const float* n2g  = (const float*)d_in[14];
    const float* n2b  = (const float*)d_in[15];
    const float* l1w  = (const float*)d_in[16];
    const float* l1b  = (const float*)d_in[17];
    const float* l2w  = (const float*)d_in[18];
    const float* l2b  = (const float*)d_in[19];
    const float* fw   = (const float*)d_in[20];
    const float* fb   = (const float*)d_in[21];
    float* out = (float*)d_out;

    __half *p_kf_hi, *p_qf_hi, *p_ctx_hi, *p_ctx_lo;
    __half *p_hn_hi, *p_hn_lo, *p_a1_hi, *p_a1_lo, *p_x_hi, *p_x_lo;
    __half *p_w_hi, *p_w_lo, *p_KVh;
    float *p_q, *p_att;
    cudaGetSymbolAddress((void**)&p_kf_hi,  g_kf_hi);
    cudaGetSymbolAddress((void**)&p_KVh,    g_KVh);
    cudaGetSymbolAddress((void**)&p_qf_hi,  g_qf_hi);
    cudaGetSymbolAddress((void**)&p_q,      g_q);
    cudaGetSymbolAddress((void**)&p_ctx_hi, g_ctx_hi);
    cudaGetSymbolAddress((void**)&p_ctx_lo, g_ctx_lo);
    cudaGetSymbolAddress((void**)&p_att,    g_att);
    cudaGetSymbolAddress((void**)&p_hn_hi,  g_hn_hi);
    cudaGetSymbolAddress((void**)&p_hn_lo,  g_hn_lo);
    cudaGetSymbolAddress((void**)&p_a1_hi,  g_a1_hi);
    cudaGetSymbolAddress((void**)&p_a1_lo,  g_a1_lo);
    cudaGetSymbolAddress((void**)&p_x_hi,   g_x_hi);
    cudaGetSymbolAddress((void**)&p_x_lo,   g_x_lo);
    cudaGetSymbolAddress((void**)&p_w_hi,   g_w_hi);
    cudaGetSymbolAddress((void**)&p_w_lo,   g_w_lo);

    // 0) weights -> fp16 hi/lo
    wsplit_kernel<<<(W_TOT + 255) / 256, 256>>>(inw, outw, l1w, l2w, fw);

    // 1) per-voxel LN + key positional feature
    kf_kernel<<<NVOX / 8, 256>>>(vf, vc, n1g, n1b, kpw, kpb);

    // 2) query positional feature
    qfeat_kernel<<<(NQ * C) / 256, 256>>>(qc, qpw, qpb);

    // 3) per-voxel K|V projection (single-pass fp16) -> fp16 [NVOX,256]
    mma_gemm<1><<<dim3(NVOX / 64, 4), 128>>>(
        p_kf_hi, nullptr, p_w_hi + W_INW + 128 * 128, nullptr,
        inb + 128, nullptr, nullptr, p_KVh, nullptr, nullptr, 256, 128, 4);

    // 4) q projection (single-pass fp16) -> fp32
    mma_gemm<1><<<dim3(NQ / 64, 2), 128>>>(
        p_qf_hi, nullptr, p_w_hi + W_INW, nullptr,
        inb, nullptr, p_q, nullptr, nullptr, nullptr, 128, 128, 8);

    // 5) sparse attention -> ctx hi/lo
    attn_kernel<<<NQ, 128>>>(kidx);

    // 6) output projection (3-pass) -> attend fp32
    mma_gemm<2><<<dim3(NQ / 64, 2), 128>>>(
        p_ctx_hi, p_ctx_lo, p_w_hi + W_OUTW, p_w_lo + W_OUTW,
        outb, nullptr, p_att, nullptr, nullptr, nullptr, 128, 128, 8);

    // 7) norm2 -> hn hi/lo
    ln_kernel<<<NQ / 8, 256>>>(p_att, n2g, n2b);

    // 8) FFN up (relu, 3-pass) -> a1 hi/lo
    mma_gemm<2><<<dim3(NQ / 64, 4), 128>>>(
        p_hn_hi, p_hn_lo, p_w_hi + W_L1W, p_w_lo + W_L1W,
        l1b, nullptr, nullptr, nullptr, p_a1_hi, p_a1_lo, 256, 128, 16 | 1);

    // 9) FFN down + residual(attend) (3-pass) -> x hi/lo
    mma_gemm<2><<<dim3(NQ / 64, 2), 128>>>(
        p_a1_hi, p_a1_lo, p_w_hi + W_L2W, p_w_lo + W_L2W,
        l2b, p_att, nullptr, nullptr, p_x_hi, p_x_lo, 128, 256, 16 | 2);

    // 10) final projection + relu (3-pass) -> output fp32
    mma_gemm<2><<<dim3(NQ / 64, 2), 128>>>(
        p_x_hi, p_x_lo, p_w_hi + W_FINW, p_w_lo + W_FINW,
        fb, nullptr, out, nullptr, nullptr, nullptr, 128, 128, 8 | 1);
}